// round 9
// baseline (speedup 1.0000x reference)
#include <cuda_runtime.h>
#include <cstdint>

// Hash-grid encoding (instant-NGP style), 2D, bilinear, 8 features.
//
// R7 redesign: counting-sort points by grid cell, then evaluate in sorted
// order. Rationale (from R4/R6 profiles): un-sorted random points put L1
// (16.7M divergent gather wavefronts), L2 (~670 MB) and DRAM (~547 MB vs
// ~194 MB compulsory) all at ~66-73% -> ~70us floor. Sorting makes warp
// lanes share table rows: gathers coalesce (~16x fewer wavefronts, table L2
// traffic 512MB -> ~40MB) and the hot table stripe becomes ~260KB so DRAM
// table traffic collapses to the ~34MB compulsory.
//
// Pipeline (all graph-capturable, no allocations; scratch = __device__ globals):
//   1. k_zero        : clear 2^20 cell counters
//   2. k_hist        : count points per cell (atomic)
//   3. k_scan_block  : per-1024-block exclusive scan of counters (in-place)
//   4. k_scan_top    : exclusive scan of 1024 block sums
//   5. k_add_offsets : add block offsets -> global exclusive bases
//   6. k_scatter     : slot = atomicAdd(base[cell]); store (x, idx) sorted
//   7. k_main        : evaluate sorted points, scatter 32B rows to out[idx]
// Within-cell order from atomics is nondeterministic, but each point's output
// is computed independently from its own x -> out is deterministic.

#define NMAX   (1 << 22)          // 4194304 points
#define NCELL  (1 << 20)          // 1024 x 1024 base cells
#define HASHMAP_MASK ((1u << 22) - 1u)

__device__ unsigned g_count[NCELL];   // counters -> exclusive bases -> cursors
__device__ unsigned g_bsum[1024];     // per-block sums for the scan
__device__ float2   g_xs[NMAX];       // cell-sorted point coords
__device__ unsigned g_pidx[NMAX];     // cell-sorted original point indices

// ---------- helpers ----------

__device__ __forceinline__ unsigned cell_of(float2 xp) {
    float fx = (xp.x + 1.0f) * 512.0f;
    float fy = (xp.y + 1.0f) * 512.0f;
    int ix = (int)fx;
    int iy = (int)fy;
    // Clamp only for binning safety (binning affects order, never values).
    ix = ix < 0 ? 0 : (ix > 1023 ? 1023 : ix);
    iy = iy < 0 ? 0 : (iy > 1023 ? 1023 : iy);
    return (unsigned)iy * 1024u + (unsigned)ix;
}

struct F8 { float v[8]; };

__device__ __forceinline__ F8 ldg_row(const float* p) {
    unsigned r0, r1, r2, r3, r4, r5, r6, r7;
    asm("ld.global.nc.L2::evict_last.v8.b32 {%0,%1,%2,%3,%4,%5,%6,%7}, [%8];"
        : "=r"(r0), "=r"(r1), "=r"(r2), "=r"(r3),
          "=r"(r4), "=r"(r5), "=r"(r6), "=r"(r7)
        : "l"(p));
    F8 o;
    o.v[0] = __uint_as_float(r0); o.v[1] = __uint_as_float(r1);
    o.v[2] = __uint_as_float(r2); o.v[3] = __uint_as_float(r3);
    o.v[4] = __uint_as_float(r4); o.v[5] = __uint_as_float(r5);
    o.v[6] = __uint_as_float(r6); o.v[7] = __uint_as_float(r7);
    return o;
}

__device__ __forceinline__ void stg_row(float* p, const F8& a) {
    asm volatile("st.global.L2::evict_first.v8.b32 [%0], {%1,%2,%3,%4,%5,%6,%7,%8};"
        :: "l"(p),
           "r"(__float_as_uint(a.v[0])), "r"(__float_as_uint(a.v[1])),
           "r"(__float_as_uint(a.v[2])), "r"(__float_as_uint(a.v[3])),
           "r"(__float_as_uint(a.v[4])), "r"(__float_as_uint(a.v[5])),
           "r"(__float_as_uint(a.v[6])), "r"(__float_as_uint(a.v[7]))
        : "memory");
}

// ---------- pipeline kernels ----------

__global__ __launch_bounds__(1024)
void k_zero() {
    g_count[blockIdx.x * 1024 + threadIdx.x] = 0u;
}

__global__ __launch_bounds__(256)
void k_hist(const float2* __restrict__ x, int n) {
    int p = blockIdx.x * blockDim.x + threadIdx.x;
    if (p >= n) return;
    atomicAdd(&g_count[cell_of(__ldg(&x[p]))], 1u);
}

// Exclusive scan of each 1024-element segment (in-place), emit segment sums.
__global__ __launch_bounds__(1024)
void k_scan_block() {
    __shared__ unsigned s[1024];
    int tid = threadIdx.x;
    int g = blockIdx.x * 1024 + tid;
    unsigned v = g_count[g];
    s[tid] = v;
    __syncthreads();
#pragma unroll
    for (int off = 1; off < 1024; off <<= 1) {
        unsigned t = (tid >= off) ? s[tid - off] : 0u;
        __syncthreads();
        s[tid] += t;
        __syncthreads();
    }
    g_count[g] = s[tid] - v;           // exclusive
    if (tid == 1023) g_bsum[blockIdx.x] = s[1023];
}

// Exclusive scan of the 1024 block sums (single block, in-place).
__global__ __launch_bounds__(1024)
void k_scan_top() {
    __shared__ unsigned s[1024];
    int tid = threadIdx.x;
    unsigned v = g_bsum[tid];
    s[tid] = v;
    __syncthreads();
#pragma unroll
    for (int off = 1; off < 1024; off <<= 1) {
        unsigned t = (tid >= off) ? s[tid - off] : 0u;
        __syncthreads();
        s[tid] += t;
        __syncthreads();
    }
    g_bsum[tid] = s[tid] - v;          // exclusive
}

__global__ __launch_bounds__(1024)
void k_add_offsets() {
    g_count[blockIdx.x * 1024 + threadIdx.x] += g_bsum[blockIdx.x];
}

__global__ __launch_bounds__(256)
void k_scatter(const float2* __restrict__ x, int n) {
    int p = blockIdx.x * blockDim.x + threadIdx.x;
    if (p >= n) return;
    float2 xp = __ldg(&x[p]);
    unsigned slot = atomicAdd(&g_count[cell_of(xp)], 1u);
    g_xs[slot]   = xp;
    g_pidx[slot] = (unsigned)p;
}

__global__ __launch_bounds__(256)
void k_main(const float* __restrict__ table, float* __restrict__ out, int n) {
    const unsigned P0 = 73856093u;
    const unsigned P1 = 19349663u;

    int i = blockIdx.x * blockDim.x + threadIdx.x;
    if (i >= n) return;

    float2 xp    = g_xs[i];
    unsigned pid = g_pidx[i];

    // (x+1)*0.5*1024 == (x+1)*512 exactly -> indices bit-identical to reference.
    float fx = (xp.x + 1.0f) * 512.0f;
    float fy = (xp.y + 1.0f) * 512.0f;
    int ix = (int)fx;
    int iy = (int)fy;
    float wx = fx - (float)ix;
    float wy = fy - (float)iy;

    unsigned hx0 = (unsigned)ix * P0;
    unsigned hx1 = hx0 + P0;
    unsigned hy0 = (unsigned)iy * P1;
    unsigned hy1 = hy0 + P1;

    unsigned i00 = (hx0 ^ hy0) & HASHMAP_MASK;
    unsigned i10 = (hx1 ^ hy0) & HASHMAP_MASK;
    unsigned i01 = (hx0 ^ hy1) & HASHMAP_MASK;
    unsigned i11 = (hx1 ^ hy1) & HASHMAP_MASK;

    float w00 = (1.0f - wx) * (1.0f - wy);
    float w10 = wx * (1.0f - wy);
    float w01 = (1.0f - wx) * wy;
    float w11 = wx * wy;

    // Warp lanes now cover ~2-3 adjacent cells -> these gathers coalesce to
    // ~8 distinct rows per warp instead of 128.
    F8 a = ldg_row(table + (size_t)i00 * 8u);
    F8 b = ldg_row(table + (size_t)i10 * 8u);
    F8 c = ldg_row(table + (size_t)i01 * 8u);
    F8 d = ldg_row(table + (size_t)i11 * 8u);

    F8 acc;
#pragma unroll
    for (int f = 0; f < 8; f++)
        acc.v[f] = a.v[f] * w00 + b.v[f] * w10 + c.v[f] * w01 + d.v[f] * w11;

    stg_row(out + (size_t)pid * 8u, acc);
}

// ---------- launch ----------

extern "C" void kernel_launch(void* const* d_in, const int* in_sizes, int n_in,
                              void* d_out, int out_size)
{
    const float2* x    = (const float2*)d_in[0];   // (N_POINTS, 2) float32
    const float* table = (const float*)d_in[1];    // (2^22, 8)  float32
    float* out         = (float*)d_out;            // (N_POINTS, 8) float32

    int n = in_sizes[0] / 2;
    if (n > NMAX) n = NMAX;
    int block = 256;
    int grid = (n + block - 1) / block;
    if (grid < 1) grid = 1;

    k_zero<<<NCELL / 1024, 1024>>>();
    k_hist<<<grid, block>>>(x, n);
    k_scan_block<<<NCELL / 1024, 1024>>>();
    k_scan_top<<<1, 1024>>>();
    k_add_offsets<<<NCELL / 1024, 1024>>>();
    k_scatter<<<grid, block>>>(x, n);
    k_main<<<grid, block>>>(table, out, n);
}